// round 14
// baseline (speedup 1.0000x reference)
#include <cuda_runtime.h>
#include <cuda_fp16.h>
#include <mma.h>
#include <math.h>
#include <stdint.h>

using namespace nvcuda;

// Problem dims
#define NFREQ 211
#define NTIME 390
#define KF    422
#define KT    1170
#define NFILT 119
#define PP    224            // padded p stride per filter
#define MPAD  26880          // = 210*128 = 120*224
#define KFOLD 1170
#define K2P   1184           // stage-2 padded K (37*32)
#define NQPAD 448
#define KP    448            // stage-1 K' (S/iT interleaved)
#define NCHUNK 14            // stage-1 K' chunks of 32
#define S1LT  10             // stage-1 l tiles of 64
#define S2MT  210            // stage-2 m-tiles of 128

#define ASCALE  0x1p-12f     // fp16 range guard on stage-1 A operand
#define PSCALE  0x1p24f      // undo (ASCALE^2) in the power epilogue

// ---------------- device scratch ----------------
__device__ __align__(16) __half g_B1h[(size_t)PP*KP];      // stage-1 coeffs [p][k']
__device__ __align__(16) __half g_E2h[(size_t)K2P*NQPAD];  // rows >=1170 stay 0
__device__ float2 g_P[(size_t)NFREQ*KT];
__device__ float2 g_X[(size_t)KF*KT];
__device__ __align__(16) __half g_Vf[(size_t)K2P*MPAD];    // folded V (scaled), rows >=1170 stay 0
__device__ float  g_Part[S2MT*4*128];

// ---------------- builders ----------------
__global__ void k_B1() {
    int i = blockIdx.x*256 + threadIdx.x;
    if (i >= PP*KP) return;
    int p = i / KP, k = i % KP;
    int kap = k >> 1; int iss = k & 1;
    float v = 0.f;
    const float inv = 1.0f/(float)KF;
    if (p < NFREQ && kap <= 211) {
        if (kap == 0)        v = iss ? 0.f : inv;
        else if (kap == 211) v = iss ? 0.f : ((p & 1) ? -inv : inv);
        else {
            int r = (kap*p) % KF;
            float s, c; sincospif(2.0f*(float)r/(float)KF, &s, &c);
            v = (iss ? s : c) * inv;
        }
    }
    g_B1h[i] = __float2half(v);
}
__global__ void k_E2() {
    int i = blockIdx.x*256 + threadIdx.x;
    if (i >= KFOLD*NQPAD) return;
    int kap = i / NQPAD, q = i % NQPAD;
    float val = 0.f;
    const float inv = 1.0f/(float)KT;
    if (q < NTIME) {
        if (kap == 0)      val = inv;
        else if (kap == 1) val = (q & 1) ? -inv : inv;
        else if (kap < 586) {
            int l = kap - 1;
            int r = (l*q) % KT;
            float s, c; sincospif(2.0f*(float)r/(float)KT, &s, &c);
            val = c * inv;
        } else {
            int l = kap - 585;
            int r = (l*q) % KT;
            float s, c; sincospif(2.0f*(float)r/(float)KT, &s, &c);
            val = -s * inv;
        }
    }
    g_E2h[(size_t)kap*NQPAD + q] = __float2half(val);
}

// ---------------- stage 0: X = fft2(pad(100*x)), 4-rotator DFT ----------------
__global__ void k_P(const float* __restrict__ x) {
    __shared__ float xs[NTIME];
    int tid = threadIdx.x;
    int u = blockIdx.y;
    for (int i = tid; i < NTIME; i += 256) xs[i] = x[u*NTIME + i] * 100.0f;
    __syncthreads();
    int l = blockIdx.x*256 + tid;
    if (l >= KT) return;
    float tr[4], ti[4], ar[4], ai[4];
    #pragma unroll
    for (int j = 0; j < 4; j++) {
        int r = (j*l) % KT;
        double sd, cd; sincospi(-2.0*r/KT, &sd, &cd);
        tr[j] = (float)cd; ti[j] = (float)sd;
        ar[j] = 0.f; ai[j] = 0.f;
    }
    int r4 = (4*l) % KT;
    double sd, cd; sincospi(-2.0*r4/KT, &sd, &cd);
    float w4r = (float)cd, w4i = (float)sd;
    for (int v = 0; v < 98; v++) {
        #pragma unroll
        for (int j = 0; j < 4; j++) {
            int uu = v*4 + j;
            float xv = (uu < NTIME) ? xs[uu] : 0.f;
            ar[j] = fmaf(xv, tr[j], ar[j]);
            ai[j] = fmaf(xv, ti[j], ai[j]);
            float nr = fmaf(tr[j], w4r, -ti[j]*w4i);
            float ni = fmaf(tr[j], w4i,  ti[j]*w4r);
            tr[j] = nr; ti[j] = ni;
        }
    }
    g_P[(size_t)u*KT + l] = make_float2((ar[0]+ar[1])+(ar[2]+ar[3]),
                                        (ai[0]+ai[1])+(ai[2]+ai[3]));
}
__global__ void k_X() {
    int tid = threadIdx.x;
    int l = blockIdx.x*256 + tid;
    int k = blockIdx.y;
    if (l >= KT) return;
    float tr[4], ti[4], xr[4], xi[4];
    #pragma unroll
    for (int j = 0; j < 4; j++) {
        int r = (j*k) % KF;
        double sd, cd; sincospi(-2.0*r/KF, &sd, &cd);
        tr[j] = (float)cd; ti[j] = (float)sd;
        xr[j] = 0.f; xi[j] = 0.f;
    }
    int r4 = (4*k) % KF;
    double sd, cd; sincospi(-2.0*r4/KF, &sd, &cd);
    float w4r = (float)cd, w4i = (float)sd;
    for (int v = 0; v < 53; v++) {
        #pragma unroll
        for (int j = 0; j < 4; j++) {
            int uu = v*4 + j;
            float2 P = (uu < NFREQ) ? g_P[(size_t)uu*KT + l] : make_float2(0.f,0.f);
            xr[j] += P.x*tr[j] - P.y*ti[j];
            xi[j] += P.x*ti[j] + P.y*tr[j];
            float nr = fmaf(tr[j], w4r, -ti[j]*w4i);
            float ni = fmaf(tr[j], w4i,  ti[j]*w4r);
            tr[j] = nr; ti[j] = ni;
        }
    }
    g_X[(size_t)k*KT + l] = make_float2((xr[0]+xr[1])+(xr[2]+xr[3]),
                                        (xi[0]+xi[1])+(xi[2]+xi[3]));
}

// freq-fold of H*X at (kap kg, time lg)
__device__ __forceinline__ void foldA(const float* __restrict__ Hre, const float* __restrict__ Him,
                                      size_t hb, int kg, int lg,
                                      float &Sx, float &Sy, float &iTx, float &iTy) {
    Sx = Sy = iTx = iTy = 0.f;
    if (kg <= 211) {
        float2 X = g_X[(size_t)kg*KT + lg];
        float hr = Hre[hb + (size_t)kg*KT + lg];
        float hi = Him[hb + (size_t)kg*KT + lg];
        float war = hr*X.x - hi*X.y;
        float wai = hr*X.y + hi*X.x;
        if (kg >= 1 && kg <= 210) {
            int km = KF - kg;
            float2 X2 = g_X[(size_t)km*KT + lg];
            float hr2 = Hre[hb + (size_t)km*KT + lg];
            float hi2 = Him[hb + (size_t)km*KT + lg];
            float wbr = hr2*X2.x - hi2*X2.y;
            float wbi = hr2*X2.y + hi2*X2.x;
            Sx = war + wbr; Sy = wai + wbi;
            float Tx = war - wbr, Ty = wai - wbi;
            iTx = -Ty; iTy = Tx;
        } else { Sx = war; Sy = wai; }
    }
}
__device__ __forceinline__ void buildA(const float* __restrict__ Hre, const float* __restrict__ Him,
                                       size_t hb, int kg, int lg, int lmg, float fm,
                                       float &cx, float &cz, float &sx, float &sz) {
    float S1x,S1y,iT1x,iT1y, S2x,S2y,iT2x,iT2y;
    foldA(Hre, Him, hb, kg, lg,  S1x, S1y, iT1x, iT1y);
    foldA(Hre, Him, hb, kg, lmg, S2x, S2y, iT2x, iT2y);
    cx = S1x + fm*S2x;  cz = iT1x + fm*iT2x;
    sx = S1y - fm*S2y;  sz = iT1y - fm*iT2y;
}

// ---------------- stage 1: fp16 WMMA GEMM, fold fused, double-buffered ----------------
// grid (S1LT, NFILT), 512 threads (16 warps: 8M x 2N).
#define ASTR 40
#define BSTR 40
#define CSTR 232
#define SM1_A0 0
#define SM1_A1 10240
#define SM1_B0 20480
#define SM1_B1 38400
#define SM1_TOT 59392          // epilogue Cs (64*232*4) overlays from 0

__global__ void __launch_bounds__(512)
k_s1mma(const float* __restrict__ Hre, const float* __restrict__ Him) {
    extern __shared__ char smem[];
    __half* Abuf[2] = { (__half*)(smem + SM1_A0), (__half*)(smem + SM1_A1) };
    __half* Bbuf[2] = { (__half*)(smem + SM1_B0), (__half*)(smem + SM1_B1) };
    float*  Cs = (float*)(smem);

    int tid = threadIdx.x;
    int f  = blockIdx.y;
    int l0 = blockIdx.x * 64;

    int wid = tid >> 5;
    int wm = wid & 7, wn = wid >> 3;
    int mb = wm * 16, nb = wn * 112;

    wmma::fragment<wmma::accumulator, 16, 16, 16, float> acc[7];
    #pragma unroll
    for (int ni = 0; ni < 7; ni++) wmma::fill_fragment(acc[ni], 0.0f);

    int lc = tid & 63;
    int kq = tid >> 6;                      // 0..7
    int lg  = l0 + lc;
    int lmg = (lg == 0) ? 0 : KT - lg;
    float fm = (lg >= 1 && lg <= 584) ? 1.0f : 0.0f;
    const size_t hb = (size_t)f * KF * KT;

    // prologue: fill buffer 0
    {
        #pragma unroll
        for (int j = 0; j < 2; j++) {
            int ka = kq + j*8;
            float cx, cz, sx, sz;
            buildA(Hre, Him, hb, ka, lg, lmg, fm, cx, cz, sx, sz);
            *(__half2*)&Abuf[0][lc*ASTR + 2*ka]      = __floats2half2_rn(cx*ASCALE, cz*ASCALE);
            *(__half2*)&Abuf[0][(64+lc)*ASTR + 2*ka] = __floats2half2_rn(sx*ASCALE, sz*ASCALE);
        }
        for (int i = tid; i < 896; i += 512) {
            int row = i >> 2, seg = i & 3;
            uint4 v = *(const uint4*)&g_B1h[(size_t)row*KP + seg*8];
            *(uint4*)&Bbuf[0][row*BSTR + seg*8] = v;
        }
    }
    __syncthreads();

    int brow = tid >> 2, bseg = tid & 3;            // B prefetch slot 1 (512 of 896)
    int brow2 = (tid+512) >> 2, bseg2 = (tid+512) & 3;  // slot 2 (tid<384)

    for (int ch = 0; ch < NCHUNK; ch++) {
        __half* Ah = Abuf[ch & 1];
        __half* Bh = Bbuf[ch & 1];
        bool hn = (ch + 1 < NCHUNK);
        float nA[2][4];
        uint4 nB0, nB1;
        if (hn) {
            #pragma unroll
            for (int j = 0; j < 2; j++) {
                int kg = (ch+1)*16 + kq + j*8;
                buildA(Hre, Him, hb, kg, lg, lmg, fm, nA[j][0], nA[j][1], nA[j][2], nA[j][3]);
            }
            nB0 = *(const uint4*)&g_B1h[(size_t)brow*KP + (ch+1)*32 + bseg*8];
            if (tid < 384)
                nB1 = *(const uint4*)&g_B1h[(size_t)brow2*KP + (ch+1)*32 + bseg2*8];
        }

        #pragma unroll
        for (int ks = 0; ks < 2; ks++) {
            wmma::fragment<wmma::matrix_a, 16, 16, 16, __half, wmma::row_major> a;
            wmma::load_matrix_sync(a, &Ah[mb*ASTR + ks*16], ASTR);
            #pragma unroll
            for (int ni = 0; ni < 7; ni++) {
                wmma::fragment<wmma::matrix_b, 16, 16, 16, __half, wmma::col_major> b;
                wmma::load_matrix_sync(b, &Bh[(nb + ni*16)*BSTR + ks*16], BSTR);
                wmma::mma_sync(acc[ni], a, b, acc[ni]);
            }
        }

        if (hn) {
            __half* An = Abuf[(ch+1) & 1];
            __half* Bn = Bbuf[(ch+1) & 1];
            #pragma unroll
            for (int j = 0; j < 2; j++) {
                int ka = kq + j*8;
                *(__half2*)&An[lc*ASTR + 2*ka]      = __floats2half2_rn(nA[j][0]*ASCALE, nA[j][1]*ASCALE);
                *(__half2*)&An[(64+lc)*ASTR + 2*ka] = __floats2half2_rn(nA[j][2]*ASCALE, nA[j][3]*ASCALE);
            }
            *(uint4*)&Bn[brow*BSTR + bseg*8] = nB0;
            if (tid < 384)
                *(uint4*)&Bn[brow2*BSTR + bseg2*8] = nB1;
        }
        __syncthreads();
    }

    // ---- two-phase epilogue: 64 rows at a time ----
    size_t fb = (size_t)f * PP;
    #pragma unroll
    for (int p = 0; p < 2; p++) {
        if ((wm >> 2) == p) {
            #pragma unroll
            for (int ni = 0; ni < 7; ni++)
                wmma::store_matrix_sync(&Cs[((wm & 3)*16)*CSTR + nb + ni*16], acc[ni],
                                        CSTR, wmma::mem_row_major);
        }
        __syncthreads();
        for (int i = tid; i < 64*28; i += 512) {
            int row = i / 28, c8 = i % 28;
            int l = l0 + row;
            int t;
            if (p == 0) t = (l == 0) ? 0 : (l == 585) ? 1 : (l >= 1 && l <= 584) ? l + 1 : -1;
            else        t = (l >= 1 && l <= 584) ? 585 + l : -1;
            if (t >= 0) {
                const float4* src = (const float4*)&Cs[row*CSTR + c8*8];
                float4 v0 = src[0], v1 = src[1];
                __half2 h0 = __floats2half2_rn(v0.x, v0.y);
                __half2 h1 = __floats2half2_rn(v0.z, v0.w);
                __half2 h2 = __floats2half2_rn(v1.x, v1.y);
                __half2 h3 = __floats2half2_rn(v1.z, v1.w);
                uint4 pk;
                pk.x = *(uint32_t*)&h0; pk.y = *(uint32_t*)&h1;
                pk.z = *(uint32_t*)&h2; pk.w = *(uint32_t*)&h3;
                *(uint4*)&g_Vf[(size_t)t*MPAD + fb + c8*8] = pk;
            }
        }
        __syncthreads();
    }
}

// ---------------- stage 2: fp16 WMMA GEMM + fused epilogue, double-buffered ----------------
// grid (2 qtiles, 210 mtiles), 512 threads (16 warps: 8M x 2N).
#define A2STR 136
#define B2STR 232
#define S2_A0 0
#define S2_A1 8704
#define S2_B0 17408
#define S2_B1 32256
#define S2_STG 47104
#define S2_TOT 63488

__global__ void __launch_bounds__(512)
k_s2mma() {
    extern __shared__ char smem[];
    __half* Abuf[2] = { (__half*)(smem + S2_A0), (__half*)(smem + S2_A1) };
    __half* Bbuf[2] = { (__half*)(smem + S2_B0), (__half*)(smem + S2_B1) };
    float*  Stg = (float*)(smem + S2_STG);

    int tid = threadIdx.x;
    int q0 = blockIdx.x * 224;
    int m0 = blockIdx.y * 128;
    int wid = tid >> 5, lane = tid & 31;
    int wm = wid & 7, wn = wid >> 3;
    int mb = wm * 16, nb = wn * 112;

    wmma::fragment<wmma::accumulator, 16, 16, 16, float> acc[7];
    #pragma unroll
    for (int ni = 0; ni < 7; ni++) wmma::fill_fragment(acc[ni], 0.0f);

    int arow = tid >> 4, aoff = tid & 15;
    int brow = tid / 28, bcol = tid % 28;
    int brow2 = (tid+512) / 28, bcol2 = (tid+512) % 28;

    // prologue: fill buffer 0
    {
        uint4 v = *(const uint4*)&g_Vf[(size_t)arow*MPAD + m0 + aoff*8];
        *(uint4*)&Abuf[0][arow*A2STR + aoff*8] = v;
        uint4 b0 = *(const uint4*)&g_E2h[(size_t)brow*NQPAD + q0 + bcol*8];
        *(uint4*)&Bbuf[0][brow*B2STR + bcol*8] = b0;
        if (tid < 384) {
            uint4 b1 = *(const uint4*)&g_E2h[(size_t)brow2*NQPAD + q0 + bcol2*8];
            *(uint4*)&Bbuf[0][brow2*B2STR + bcol2*8] = b1;
        }
    }
    __syncthreads();

    for (int ch = 0; ch < 37; ch++) {
        __half* As = Abuf[ch & 1];
        __half* Bs = Bbuf[ch & 1];
        bool hn = (ch + 1 < 37);
        uint4 pa, pb0, pb1;
        if (hn) {
            int kb = (ch+1)*32;
            pa  = *(const uint4*)&g_Vf[(size_t)(kb+arow)*MPAD + m0 + aoff*8];
            pb0 = *(const uint4*)&g_E2h[(size_t)(kb+brow)*NQPAD + q0 + bcol*8];
            if (tid < 384)
                pb1 = *(const uint4*)&g_E2h[(size_t)(kb+brow2)*NQPAD + q0 + bcol2*8];
        }

        #pragma unroll
        for (int ks = 0; ks < 2; ks++) {
            wmma::fragment<wmma::matrix_a, 16, 16, 16, __half, wmma::col_major> a;
            wmma::load_matrix_sync(a, &As[(ks*16)*A2STR + mb], A2STR);
            #pragma unroll
            for (int ni = 0; ni < 7; ni++) {
                wmma::fragment<wmma::matrix_b, 16, 16, 16, __half, wmma::row_major> b;
                wmma::load_matrix_sync(b, &Bs[(ks*16)*B2STR + nb + ni*16], B2STR);
                wmma::mma_sync(acc[ni], a, b, acc[ni]);
            }
        }

        if (hn) {
            __half* An = Abuf[(ch+1) & 1];
            __half* Bn = Bbuf[(ch+1) & 1];
            *(uint4*)&An[arow*A2STR + aoff*8] = pa;
            *(uint4*)&Bn[brow*B2STR + bcol*8] = pb0;
            if (tid < 384)
                *(uint4*)&Bn[brow2*B2STR + bcol2*8] = pb1;
        }
        __syncthreads();
    }

    // ---- fused epilogue: per-warp staging, rescaled clamp-power row sums ----
    float* st = &Stg[wid*256];
    int r0 = lane >> 1, half = lane & 1;
    float rs = 0.f;
    #pragma unroll
    for (int ni = 0; ni < 7; ni++) {
        wmma::store_matrix_sync(st, acc[ni], 16, wmma::mem_row_major);
        __syncwarp();
        int qbase = q0 + nb + ni*16 + half*8;
        #pragma unroll
        for (int c = 0; c < 8; c++) {
            float v = st[r0*16 + half*8 + c];
            if (qbase + c < NTIME) rs += fmaxf(v*v*PSCALE, 1e-8f);
        }
        __syncwarp();
    }
    rs += __shfl_down_sync(0xffffffffu, rs, 1);
    int mrow = mb + r0;
    int m = m0 + mrow;
    int ff = m / PP, p = m - ff*PP;
    bool mok = (p < NFREQ) && (ff < NFILT);
    if (half == 0)
        g_Part[((blockIdx.y*2 + blockIdx.x)*2 + wn)*128 + mrow] = mok ? rs : 0.f;
}

// ---------------- finalize ----------------
__global__ void k_fin(float* __restrict__ out) {
    int f = threadIdx.x;
    if (f >= NFILT) return;
    float s = 0.f;
    for (int p = 0; p < NFREQ; p++) {
        int m = f*PP + p;
        int mt = m >> 7, r = m & 127;
        #pragma unroll
        for (int sl = 0; sl < 4; sl++)
            s += g_Part[(mt*4 + sl)*128 + r];
    }
    out[f] = s * (1.0f / (float)(NFREQ*NTIME));
}

// ---------------- launch ----------------
extern "C" void kernel_launch(void* const* d_in, const int* in_sizes, int n_in,
                              void* d_out, int out_size) {
    (void)in_sizes; (void)n_in; (void)out_size;
    const float* x   = (const float*)d_in[0];
    const float* Hre = (const float*)d_in[1];
    const float* Him = (const float*)d_in[2];
    float* out = (float*)d_out;

    cudaFuncSetAttribute(k_s1mma, cudaFuncAttributeMaxDynamicSharedMemorySize, SM1_TOT);
    cudaFuncSetAttribute(k_s2mma, cudaFuncAttributeMaxDynamicSharedMemorySize, S2_TOT);

    k_B1    <<<(PP*KP + 255)/256, 256>>>();
    k_E2    <<<(KFOLD*NQPAD + 255)/256, 256>>>();
    k_P     <<<dim3(5, NFREQ), 256>>>(x);
    k_X     <<<dim3(5, KF),    256>>>();
    k_s1mma <<<dim3(S1LT, NFILT), 512, SM1_TOT>>>(Hre, Him);
    k_s2mma <<<dim3(2, S2MT), 512, S2_TOT>>>();
    k_fin   <<<1, 128>>>(out);
}

// round 15
// speedup vs baseline: 1.2125x; 1.2125x over previous
#include <cuda_runtime.h>
#include <cuda_fp16.h>
#include <mma.h>
#include <math.h>
#include <stdint.h>

using namespace nvcuda;

// Problem dims
#define NFREQ 211
#define NTIME 390
#define KF    422
#define KT    1170
#define NFILT 119
#define PP    224            // padded p stride per filter
#define MPAD  26880          // = 210*128 = 120*224
#define KFOLD 1170
#define K2P   1184           // stage-2 padded K (37*32)
#define NQPAD 448
#define KP    448            // stage-1 K' (S/iT interleaved)
#define NCHUNK 14            // stage-1 K' chunks of 32
#define S1LT  10             // stage-1 l tiles of 64
#define S2MT  210            // stage-2 m-tiles of 128

#define ASCALE  0x1p-12f     // fp16 range guard on stage-1 A operand
#define PSCALE  0x1p24f      // undo (ASCALE^2) in the power epilogue

// ---------------- device scratch ----------------
__device__ __align__(8)  float2 g_twT[KT];                 // e^{-2pi i j/KT}
__device__ __align__(8)  float2 g_twF[KF];                 // e^{-2pi i j/KF}
__device__ __align__(16) __half g_B1h[(size_t)PP*KP];      // stage-1 coeffs [p][k']
__device__ __align__(16) __half g_E2h[(size_t)K2P*NQPAD];  // rows >=1170 stay 0
__device__ float2 g_P[(size_t)(NFREQ+1)*KT];               // row 211 stays 0 (pad)
__device__ float2 g_X[(size_t)KF*KT];
__device__ __align__(16) __half g_Vf[(size_t)K2P*MPAD];    // folded V (scaled), rows >=1170 stay 0
__device__ float  g_Part[S2MT*4*128];

// ---------------- builders ----------------
__global__ void k_tw() {
    int i = blockIdx.x*256 + threadIdx.x;
    if (i < KT) { double s,c; sincospi(2.0*i/KT, &s, &c); g_twT[i] = make_float2((float)c, (float)(-s)); }
    if (i < KF) { double s,c; sincospi(2.0*i/KF, &s, &c); g_twF[i] = make_float2((float)c, (float)(-s)); }
}
__global__ void k_B1() {
    int i = blockIdx.x*256 + threadIdx.x;
    if (i >= PP*KP) return;
    int p = i / KP, k = i % KP;
    int kap = k >> 1; int iss = k & 1;
    float v = 0.f;
    const float inv = 1.0f/(float)KF;
    if (p < NFREQ && kap <= 211) {
        if (kap == 0)        v = iss ? 0.f : inv;
        else if (kap == 211) v = iss ? 0.f : ((p & 1) ? -inv : inv);
        else {
            int r = (kap*p) % KF;
            float s, c; sincospif(2.0f*(float)r/(float)KF, &s, &c);
            v = (iss ? s : c) * inv;
        }
    }
    g_B1h[i] = __float2half(v);
}
__global__ void k_E2() {
    int i = blockIdx.x*256 + threadIdx.x;
    if (i >= KFOLD*NQPAD) return;
    int kap = i / NQPAD, q = i % NQPAD;
    float val = 0.f;
    const float inv = 1.0f/(float)KT;
    if (q < NTIME) {
        if (kap == 0)      val = inv;
        else if (kap == 1) val = (q & 1) ? -inv : inv;
        else if (kap < 586) {
            int l = kap - 1;
            int r = (l*q) % KT;
            float s, c; sincospif(2.0f*(float)r/(float)KT, &s, &c);
            val = c * inv;
        } else {
            int l = kap - 585;
            int r = (l*q) % KT;
            float s, c; sincospif(2.0f*(float)r/(float)KT, &s, &c);
            val = -s * inv;
        }
    }
    g_E2h[(size_t)kap*NQPAD + q] = __float2half(val);
}

// ---------------- stage 0: X = fft2(pad(100*x)), 4-rotator DFT, table init ----------------
__global__ void k_P(const float* __restrict__ x) {
    __shared__ float xs[392];
    int tid = threadIdx.x;
    int u = blockIdx.y;
    for (int i = tid; i < 392; i += 256) xs[i] = (i < NTIME) ? x[u*NTIME + i] * 100.0f : 0.f;
    __syncthreads();
    int l = blockIdx.x*256 + tid;
    if (l >= KT) return;
    float tr[4], ti[4], ar[4], ai[4];
    #pragma unroll
    for (int j = 0; j < 4; j++) {
        float2 t = g_twT[(j*l) % KT];
        tr[j] = t.x; ti[j] = t.y;
        ar[j] = 0.f; ai[j] = 0.f;
    }
    float2 w4 = g_twT[(4*l) % KT];
    float w4r = w4.x, w4i = w4.y;
    for (int v = 0; v < 98; v++) {
        #pragma unroll
        for (int j = 0; j < 4; j++) {
            float xv = xs[v*4 + j];
            ar[j] = fmaf(xv, tr[j], ar[j]);
            ai[j] = fmaf(xv, ti[j], ai[j]);
            float nr = fmaf(tr[j], w4r, -ti[j]*w4i);
            float ni = fmaf(tr[j], w4i,  ti[j]*w4r);
            tr[j] = nr; ti[j] = ni;
        }
    }
    g_P[(size_t)u*KT + l] = make_float2((ar[0]+ar[1])+(ar[2]+ar[3]),
                                        (ai[0]+ai[1])+(ai[2]+ai[3]));
}
__global__ void k_X() {
    int tid = threadIdx.x;
    int l = blockIdx.x*256 + tid;
    int k = blockIdx.y;
    if (l >= KT) return;
    float tr[4], ti[4], xr[4], xi[4];
    #pragma unroll
    for (int j = 0; j < 4; j++) {
        float2 t = g_twF[(j*k) % KF];
        tr[j] = t.x; ti[j] = t.y;
        xr[j] = 0.f; xi[j] = 0.f;
    }
    float2 w4 = g_twF[(4*k) % KF];
    float w4r = w4.x, w4i = w4.y;
    for (int v = 0; v < 53; v++) {
        #pragma unroll
        for (int j = 0; j < 4; j++) {
            float2 P = g_P[(size_t)(v*4 + j)*KT + l];   // row 211 = zeros (pad)
            xr[j] += P.x*tr[j] - P.y*ti[j];
            xi[j] += P.x*ti[j] + P.y*tr[j];
            float nr = fmaf(tr[j], w4r, -ti[j]*w4i);
            float ni = fmaf(tr[j], w4i,  ti[j]*w4r);
            tr[j] = nr; ti[j] = ni;
        }
    }
    g_X[(size_t)k*KT + l] = make_float2((xr[0]+xr[1])+(xr[2]+xr[3]),
                                        (xi[0]+xi[1])+(xi[2]+xi[3]));
}

// freq-fold of H*X at (kap kg, time lg)
__device__ __forceinline__ void foldA(const float* __restrict__ Hre, const float* __restrict__ Him,
                                      size_t hb, int kg, int lg,
                                      float &Sx, float &Sy, float &iTx, float &iTy) {
    Sx = Sy = iTx = iTy = 0.f;
    if (kg <= 211) {
        float2 X = g_X[(size_t)kg*KT + lg];
        float hr = Hre[hb + (size_t)kg*KT + lg];
        float hi = Him[hb + (size_t)kg*KT + lg];
        float war = hr*X.x - hi*X.y;
        float wai = hr*X.y + hi*X.x;
        if (kg >= 1 && kg <= 210) {
            int km = KF - kg;
            float2 X2 = g_X[(size_t)km*KT + lg];
            float hr2 = Hre[hb + (size_t)km*KT + lg];
            float hi2 = Him[hb + (size_t)km*KT + lg];
            float wbr = hr2*X2.x - hi2*X2.y;
            float wbi = hr2*X2.y + hi2*X2.x;
            Sx = war + wbr; Sy = wai + wbi;
            float Tx = war - wbr, Ty = wai - wbi;
            iTx = -Ty; iTy = Tx;
        } else { Sx = war; Sy = wai; }
    }
}
__device__ __forceinline__ void buildA(const float* __restrict__ Hre, const float* __restrict__ Him,
                                       size_t hb, int kg, int lg, int lmg, float fm,
                                       float &cx, float &cz, float &sx, float &sz) {
    float S1x,S1y,iT1x,iT1y, S2x,S2y,iT2x,iT2y;
    foldA(Hre, Him, hb, kg, lg,  S1x, S1y, iT1x, iT1y);
    foldA(Hre, Him, hb, kg, lmg, S2x, S2y, iT2x, iT2y);
    cx = S1x + fm*S2x;  cz = iT1x + fm*iT2x;
    sx = S1y - fm*S2y;  sz = iT1y - fm*iT2y;
}

// ---------------- stage 1: fp16 WMMA GEMM, fold fused, double-buffered ----------------
// grid (S1LT, NFILT), 512 threads (16 warps: 8M x 2N).
#define ASTR 40
#define BSTR 40
#define CSTR 232
#define SM1_A0 0
#define SM1_A1 10240
#define SM1_B0 20480
#define SM1_B1 38400
#define SM1_TOT 59392          // epilogue Cs (64*232*4) overlays from 0

__global__ void __launch_bounds__(512)
k_s1mma(const float* __restrict__ Hre, const float* __restrict__ Him) {
    extern __shared__ char smem[];
    __half* Abuf[2] = { (__half*)(smem + SM1_A0), (__half*)(smem + SM1_A1) };
    __half* Bbuf[2] = { (__half*)(smem + SM1_B0), (__half*)(smem + SM1_B1) };
    float*  Cs = (float*)(smem);

    int tid = threadIdx.x;
    int f  = blockIdx.y;
    int l0 = blockIdx.x * 64;

    int wid = tid >> 5;
    int wm = wid & 7, wn = wid >> 3;
    int mb = wm * 16, nb = wn * 112;

    wmma::fragment<wmma::accumulator, 16, 16, 16, float> acc[7];
    #pragma unroll
    for (int ni = 0; ni < 7; ni++) wmma::fill_fragment(acc[ni], 0.0f);

    int lc = tid & 63;
    int kq = tid >> 6;                      // 0..7
    int lg  = l0 + lc;
    int lmg = (lg == 0) ? 0 : KT - lg;
    float fm = (lg >= 1 && lg <= 584) ? 1.0f : 0.0f;
    const size_t hb = (size_t)f * KF * KT;

    // prologue: fill buffer 0
    {
        #pragma unroll
        for (int j = 0; j < 2; j++) {
            int ka = kq + j*8;
            float cx, cz, sx, sz;
            buildA(Hre, Him, hb, ka, lg, lmg, fm, cx, cz, sx, sz);
            *(__half2*)&Abuf[0][lc*ASTR + 2*ka]      = __floats2half2_rn(cx*ASCALE, cz*ASCALE);
            *(__half2*)&Abuf[0][(64+lc)*ASTR + 2*ka] = __floats2half2_rn(sx*ASCALE, sz*ASCALE);
        }
        for (int i = tid; i < 896; i += 512) {
            int row = i >> 2, seg = i & 3;
            uint4 v = *(const uint4*)&g_B1h[(size_t)row*KP + seg*8];
            *(uint4*)&Bbuf[0][row*BSTR + seg*8] = v;
        }
    }
    __syncthreads();

    int brow = tid >> 2, bseg = tid & 3;
    int brow2 = (tid+512) >> 2, bseg2 = (tid+512) & 3;

    for (int ch = 0; ch < NCHUNK; ch++) {
        __half* Ah = Abuf[ch & 1];
        __half* Bh = Bbuf[ch & 1];
        bool hn = (ch + 1 < NCHUNK);
        float nA[2][4];
        uint4 nB0, nB1;
        if (hn) {
            #pragma unroll
            for (int j = 0; j < 2; j++) {
                int kg = (ch+1)*16 + kq + j*8;
                buildA(Hre, Him, hb, kg, lg, lmg, fm, nA[j][0], nA[j][1], nA[j][2], nA[j][3]);
            }
            nB0 = *(const uint4*)&g_B1h[(size_t)brow*KP + (ch+1)*32 + bseg*8];
            if (tid < 384)
                nB1 = *(const uint4*)&g_B1h[(size_t)brow2*KP + (ch+1)*32 + bseg2*8];
        }

        #pragma unroll
        for (int ks = 0; ks < 2; ks++) {
            wmma::fragment<wmma::matrix_a, 16, 16, 16, __half, wmma::row_major> a;
            wmma::load_matrix_sync(a, &Ah[mb*ASTR + ks*16], ASTR);
            #pragma unroll
            for (int ni = 0; ni < 7; ni++) {
                wmma::fragment<wmma::matrix_b, 16, 16, 16, __half, wmma::col_major> b;
                wmma::load_matrix_sync(b, &Bh[(nb + ni*16)*BSTR + ks*16], BSTR);
                wmma::mma_sync(acc[ni], a, b, acc[ni]);
            }
        }

        if (hn) {
            __half* An = Abuf[(ch+1) & 1];
            __half* Bn = Bbuf[(ch+1) & 1];
            #pragma unroll
            for (int j = 0; j < 2; j++) {
                int ka = kq + j*8;
                *(__half2*)&An[lc*ASTR + 2*ka]      = __floats2half2_rn(nA[j][0]*ASCALE, nA[j][1]*ASCALE);
                *(__half2*)&An[(64+lc)*ASTR + 2*ka] = __floats2half2_rn(nA[j][2]*ASCALE, nA[j][3]*ASCALE);
            }
            *(uint4*)&Bn[brow*BSTR + bseg*8] = nB0;
            if (tid < 384)
                *(uint4*)&Bn[brow2*BSTR + bseg2*8] = nB1;
        }
        __syncthreads();
    }

    // ---- two-phase epilogue: 64 rows at a time ----
    size_t fb = (size_t)f * PP;
    #pragma unroll
    for (int p = 0; p < 2; p++) {
        if ((wm >> 2) == p) {
            #pragma unroll
            for (int ni = 0; ni < 7; ni++)
                wmma::store_matrix_sync(&Cs[((wm & 3)*16)*CSTR + nb + ni*16], acc[ni],
                                        CSTR, wmma::mem_row_major);
        }
        __syncthreads();
        for (int i = tid; i < 64*28; i += 512) {
            int row = i / 28, c8 = i % 28;
            int l = l0 + row;
            int t;
            if (p == 0) t = (l == 0) ? 0 : (l == 585) ? 1 : (l >= 1 && l <= 584) ? l + 1 : -1;
            else        t = (l >= 1 && l <= 584) ? 585 + l : -1;
            if (t >= 0) {
                const float4* src = (const float4*)&Cs[row*CSTR + c8*8];
                float4 v0 = src[0], v1 = src[1];
                __half2 h0 = __floats2half2_rn(v0.x, v0.y);
                __half2 h1 = __floats2half2_rn(v0.z, v0.w);
                __half2 h2 = __floats2half2_rn(v1.x, v1.y);
                __half2 h3 = __floats2half2_rn(v1.z, v1.w);
                uint4 pk;
                pk.x = *(uint32_t*)&h0; pk.y = *(uint32_t*)&h1;
                pk.z = *(uint32_t*)&h2; pk.w = *(uint32_t*)&h3;
                *(uint4*)&g_Vf[(size_t)t*MPAD + fb + c8*8] = pk;
            }
        }
        __syncthreads();
    }
}

// ---------------- stage 2: fp16 WMMA GEMM + fused epilogue, double-buffered ----------------
// grid (2 qtiles, 210 mtiles), 512 threads (16 warps: 8M x 2N).
#define A2STR 136
#define B2STR 232
#define S2_A0 0
#define S2_A1 8704
#define S2_B0 17408
#define S2_B1 32256
#define S2_STG 47104
#define S2_TOT 63488

__global__ void __launch_bounds__(512)
k_s2mma() {
    extern __shared__ char smem[];
    __half* Abuf[2] = { (__half*)(smem + S2_A0), (__half*)(smem + S2_A1) };
    __half* Bbuf[2] = { (__half*)(smem + S2_B0), (__half*)(smem + S2_B1) };
    float*  Stg = (float*)(smem + S2_STG);

    int tid = threadIdx.x;
    int q0 = blockIdx.x * 224;
    int m0 = blockIdx.y * 128;
    int wid = tid >> 5, lane = tid & 31;
    int wm = wid & 7, wn = wid >> 3;
    int mb = wm * 16, nb = wn * 112;

    wmma::fragment<wmma::accumulator, 16, 16, 16, float> acc[7];
    #pragma unroll
    for (int ni = 0; ni < 7; ni++) wmma::fill_fragment(acc[ni], 0.0f);

    int arow = tid >> 4, aoff = tid & 15;
    int brow = tid / 28, bcol = tid % 28;
    int brow2 = (tid+512) / 28, bcol2 = (tid+512) % 28;

    // prologue: fill buffer 0
    {
        uint4 v = *(const uint4*)&g_Vf[(size_t)arow*MPAD + m0 + aoff*8];
        *(uint4*)&Abuf[0][arow*A2STR + aoff*8] = v;
        uint4 b0 = *(const uint4*)&g_E2h[(size_t)brow*NQPAD + q0 + bcol*8];
        *(uint4*)&Bbuf[0][brow*B2STR + bcol*8] = b0;
        if (tid < 384) {
            uint4 b1 = *(const uint4*)&g_E2h[(size_t)brow2*NQPAD + q0 + bcol2*8];
            *(uint4*)&Bbuf[0][brow2*B2STR + bcol2*8] = b1;
        }
    }
    __syncthreads();

    for (int ch = 0; ch < 37; ch++) {
        __half* As = Abuf[ch & 1];
        __half* Bs = Bbuf[ch & 1];
        bool hn = (ch + 1 < 37);
        uint4 pa, pb0, pb1;
        if (hn) {
            int kb = (ch+1)*32;
            pa  = *(const uint4*)&g_Vf[(size_t)(kb+arow)*MPAD + m0 + aoff*8];
            pb0 = *(const uint4*)&g_E2h[(size_t)(kb+brow)*NQPAD + q0 + bcol*8];
            if (tid < 384)
                pb1 = *(const uint4*)&g_E2h[(size_t)(kb+brow2)*NQPAD + q0 + bcol2*8];
        }

        #pragma unroll
        for (int ks = 0; ks < 2; ks++) {
            wmma::fragment<wmma::matrix_a, 16, 16, 16, __half, wmma::col_major> a;
            wmma::load_matrix_sync(a, &As[(ks*16)*A2STR + mb], A2STR);
            #pragma unroll
            for (int ni = 0; ni < 7; ni++) {
                wmma::fragment<wmma::matrix_b, 16, 16, 16, __half, wmma::row_major> b;
                wmma::load_matrix_sync(b, &Bs[(ks*16)*B2STR + nb + ni*16], B2STR);
                wmma::mma_sync(acc[ni], a, b, acc[ni]);
            }
        }

        if (hn) {
            __half* An = Abuf[(ch+1) & 1];
            __half* Bn = Bbuf[(ch+1) & 1];
            *(uint4*)&An[arow*A2STR + aoff*8] = pa;
            *(uint4*)&Bn[brow*B2STR + bcol*8] = pb0;
            if (tid < 384)
                *(uint4*)&Bn[brow2*B2STR + bcol2*8] = pb1;
        }
        __syncthreads();
    }

    // ---- fused epilogue: per-warp staging, rescaled clamp-power row sums ----
    float* st = &Stg[wid*256];
    int r0 = lane >> 1, half = lane & 1;
    float rs = 0.f;
    #pragma unroll
    for (int ni = 0; ni < 7; ni++) {
        wmma::store_matrix_sync(st, acc[ni], 16, wmma::mem_row_major);
        __syncwarp();
        int qbase = q0 + nb + ni*16 + half*8;
        #pragma unroll
        for (int c = 0; c < 8; c++) {
            float v = st[r0*16 + half*8 + c];
            if (qbase + c < NTIME) rs += fmaxf(v*v*PSCALE, 1e-8f);
        }
        __syncwarp();
    }
    rs += __shfl_down_sync(0xffffffffu, rs, 1);
    int mrow = mb + r0;
    int m = m0 + mrow;
    int ff = m / PP, p = m - ff*PP;
    bool mok = (p < NFREQ) && (ff < NFILT);
    if (half == 0)
        g_Part[((blockIdx.y*2 + blockIdx.x)*2 + wn)*128 + mrow] = mok ? rs : 0.f;
}

// ---------------- finalize ----------------
__global__ void k_fin(float* __restrict__ out) {
    int f = threadIdx.x;
    if (f >= NFILT) return;
    float s = 0.f;
    for (int p = 0; p < NFREQ; p++) {
        int m = f*PP + p;
        int mt = m >> 7, r = m & 127;
        #pragma unroll
        for (int sl = 0; sl < 4; sl++)
            s += g_Part[(mt*4 + sl)*128 + r];
    }
    out[f] = s * (1.0f / (float)(NFREQ*NTIME));
}

// ---------------- launch ----------------
extern "C" void kernel_launch(void* const* d_in, const int* in_sizes, int n_in,
                              void* d_out, int out_size) {
    (void)in_sizes; (void)n_in; (void)out_size;
    const float* x   = (const float*)d_in[0];
    const float* Hre = (const float*)d_in[1];
    const float* Him = (const float*)d_in[2];
    float* out = (float*)d_out;

    cudaFuncSetAttribute(k_s1mma, cudaFuncAttributeMaxDynamicSharedMemorySize, SM1_TOT);
    cudaFuncSetAttribute(k_s2mma, cudaFuncAttributeMaxDynamicSharedMemorySize, S2_TOT);

    k_tw    <<<5, 256>>>();
    k_B1    <<<(PP*KP + 255)/256, 256>>>();
    k_E2    <<<(KFOLD*NQPAD + 255)/256, 256>>>();
    k_P     <<<dim3(5, NFREQ), 256>>>(x);
    k_X     <<<dim3(5, KF),    256>>>();
    k_s1mma <<<dim3(S1LT, NFILT), 512, SM1_TOT>>>(Hre, Him);
    k_s2mma <<<dim3(2, S2MT), 512, S2_TOT>>>();
    k_fin   <<<1, 128>>>(out);
}

// round 16
// speedup vs baseline: 1.3002x; 1.0723x over previous
#include <cuda_runtime.h>
#include <cuda_fp16.h>
#include <mma.h>
#include <math.h>
#include <stdint.h>

using namespace nvcuda;

// Problem dims
#define NFREQ 211
#define NTIME 390
#define KF    422
#define KT    1170
#define NFILT 119
#define PP    224            // padded p stride per filter
#define MPAD  26880          // = 210*128 = 120*224
#define KFOLD 1170
#define K2P   1184           // stage-2 padded K (37*32)
#define NQPAD 448
#define KP    448            // stage-1 K' (S/iT interleaved)
#define NCHUNK 14            // stage-1 K' chunks of 32 (last chunk half)
#define NPAIR  69615         // 585 * 119 row-pairs
#define S1TILES 1088         // ceil(NPAIR/64)
#define S2MT  210            // stage-2 m-tiles of 128

#define ASCALE  0x1p-12f     // fp16 range guard on stage-1 A operand
#define PSCALE  0x1p24f      // undo (ASCALE^2) in the power epilogue

// ---------------- device scratch ----------------
__device__ __align__(8)  float2 g_twT[KT];                 // e^{-2pi i j/KT}
__device__ __align__(8)  float2 g_twF[KF];                 // e^{-2pi i j/KF}
__device__ __align__(16) __half g_B1h[(size_t)PP*KP];      // stage-1 coeffs [p][k']
__device__ __align__(16) __half g_E2h[(size_t)K2P*NQPAD];  // rows >=1170 stay 0
__device__ float2 g_P[(size_t)(NFREQ+1)*KT];               // row 211 stays 0 (pad)
__device__ float2 g_X[(size_t)KF*KT];
__device__ __align__(16) __half g_Vf[(size_t)K2P*MPAD];    // folded V (scaled), rows >=1170 stay 0
__device__ float  g_Part[S2MT*4*128];

// ---------------- builders ----------------
__global__ void k_tw() {
    int i = blockIdx.x*256 + threadIdx.x;
    if (i < KT) { double s,c; sincospi(2.0*i/KT, &s, &c); g_twT[i] = make_float2((float)c, (float)(-s)); }
    if (i < KF) { double s,c; sincospi(2.0*i/KF, &s, &c); g_twF[i] = make_float2((float)c, (float)(-s)); }
}
__global__ void k_B1() {
    int i = blockIdx.x*256 + threadIdx.x;
    if (i >= PP*KP) return;
    int p = i / KP, k = i % KP;
    int kap = k >> 1; int iss = k & 1;
    float v = 0.f;
    const float inv = 1.0f/(float)KF;
    if (p < NFREQ && kap <= 211) {
        if (kap == 0)        v = iss ? 0.f : inv;
        else if (kap == 211) v = iss ? 0.f : ((p & 1) ? -inv : inv);
        else {
            int r = (kap*p) % KF;
            float s, c; sincospif(2.0f*(float)r/(float)KF, &s, &c);
            v = (iss ? s : c) * inv;
        }
    }
    g_B1h[i] = __float2half(v);
}
__global__ void k_E2() {
    int i = blockIdx.x*256 + threadIdx.x;
    if (i >= KFOLD*NQPAD) return;
    int kap = i / NQPAD, q = i % NQPAD;
    float val = 0.f;
    const float inv = 1.0f/(float)KT;
    if (q < NTIME) {
        if (kap == 0)      val = inv;
        else if (kap == 1) val = (q & 1) ? -inv : inv;
        else if (kap < 586) {
            int l = kap - 1;
            int r = (l*q) % KT;
            float s, c; sincospif(2.0f*(float)r/(float)KT, &s, &c);
            val = c * inv;
        } else {
            int l = kap - 585;
            int r = (l*q) % KT;
            float s, c; sincospif(2.0f*(float)r/(float)KT, &s, &c);
            val = -s * inv;
        }
    }
    g_E2h[(size_t)kap*NQPAD + q] = __float2half(val);
}

// ---------------- stage 0: X = fft2(pad(100*x)), 4-rotator DFT, table init ----------------
__global__ void k_P(const float* __restrict__ x) {
    __shared__ float xs[392];
    int tid = threadIdx.x;
    int u = blockIdx.y;
    for (int i = tid; i < 392; i += 256) xs[i] = (i < NTIME) ? x[u*NTIME + i] * 100.0f : 0.f;
    __syncthreads();
    int l = blockIdx.x*256 + tid;
    if (l >= KT) return;
    float tr[4], ti[4], ar[4], ai[4];
    #pragma unroll
    for (int j = 0; j < 4; j++) {
        float2 t = g_twT[(j*l) % KT];
        tr[j] = t.x; ti[j] = t.y;
        ar[j] = 0.f; ai[j] = 0.f;
    }
    float2 w4 = g_twT[(4*l) % KT];
    float w4r = w4.x, w4i = w4.y;
    for (int v = 0; v < 98; v++) {
        #pragma unroll
        for (int j = 0; j < 4; j++) {
            float xv = xs[v*4 + j];
            ar[j] = fmaf(xv, tr[j], ar[j]);
            ai[j] = fmaf(xv, ti[j], ai[j]);
            float nr = fmaf(tr[j], w4r, -ti[j]*w4i);
            float ni = fmaf(tr[j], w4i,  ti[j]*w4r);
            tr[j] = nr; ti[j] = ni;
        }
    }
    g_P[(size_t)u*KT + l] = make_float2((ar[0]+ar[1])+(ar[2]+ar[3]),
                                        (ai[0]+ai[1])+(ai[2]+ai[3]));
}
__global__ void k_X() {
    int tid = threadIdx.x;
    int l = blockIdx.x*256 + tid;
    int k = blockIdx.y;
    if (l >= KT) return;
    float tr[4], ti[4], xr[4], xi[4];
    #pragma unroll
    for (int j = 0; j < 4; j++) {
        float2 t = g_twF[(j*k) % KF];
        tr[j] = t.x; ti[j] = t.y;
        xr[j] = 0.f; xi[j] = 0.f;
    }
    float2 w4 = g_twF[(4*k) % KF];
    float w4r = w4.x, w4i = w4.y;
    for (int v = 0; v < 53; v++) {
        #pragma unroll
        for (int j = 0; j < 4; j++) {
            float2 P = g_P[(size_t)(v*4 + j)*KT + l];   // row 211 = zeros (pad)
            xr[j] += P.x*tr[j] - P.y*ti[j];
            xi[j] += P.x*ti[j] + P.y*tr[j];
            float nr = fmaf(tr[j], w4r, -ti[j]*w4i);
            float ni = fmaf(tr[j], w4i,  ti[j]*w4r);
            tr[j] = nr; ti[j] = ni;
        }
    }
    g_X[(size_t)k*KT + l] = make_float2((xr[0]+xr[1])+(xr[2]+xr[3]),
                                        (xi[0]+xi[1])+(xi[2]+xi[3]));
}

// freq-fold of H*X at (kap kg, time lg); H streamed (read-once) via __ldcs
__device__ __forceinline__ void foldA(const float* __restrict__ Hre, const float* __restrict__ Him,
                                      size_t hb, int kg, int lg,
                                      float &Sx, float &Sy, float &iTx, float &iTy) {
    Sx = Sy = iTx = iTy = 0.f;
    if (kg <= 211) {
        float2 X = g_X[(size_t)kg*KT + lg];
        float hr = __ldcs(&Hre[hb + (size_t)kg*KT + lg]);
        float hi = __ldcs(&Him[hb + (size_t)kg*KT + lg]);
        float war = hr*X.x - hi*X.y;
        float wai = hr*X.y + hi*X.x;
        if (kg >= 1 && kg <= 210) {
            int km = KF - kg;
            float2 X2 = g_X[(size_t)km*KT + lg];
            float hr2 = __ldcs(&Hre[hb + (size_t)km*KT + lg]);
            float hi2 = __ldcs(&Him[hb + (size_t)km*KT + lg]);
            float wbr = hr2*X2.x - hi2*X2.y;
            float wbi = hr2*X2.y + hi2*X2.x;
            Sx = war + wbr; Sy = wai + wbi;
            float Tx = war - wbr, Ty = wai - wbi;
            iTx = -Ty; iTy = Tx;
        } else { Sx = war; Sy = wai; }
    }
}
// one pair: cos row (c0,c1) and sin row (s0,s1); special pair (lp==0) packs cos@0 + cos@585
__device__ __forceinline__ void buildRows(const float* __restrict__ Hre, const float* __restrict__ Him,
                                          size_t hb, int kg, int lgA, int lgB, bool special, bool valid,
                                          float &c0, float &c1, float &s0, float &s1v) {
    float SxA,SyA,iTxA,iTyA, SxB,SyB,iTxB,iTyB;
    foldA(Hre, Him, hb, kg, lgA, SxA, SyA, iTxA, iTyA);
    foldA(Hre, Him, hb, kg, lgB, SxB, SyB, iTxB, iTyB);
    if (special) { c0 = SxA; c1 = iTxA; s0 = SxB; s1v = iTxB; }
    else         { c0 = SxA+SxB; c1 = iTxA+iTxB; s0 = SyA-SyB; s1v = iTyA-iTyB; }
    if (!valid)  { c0 = c1 = s0 = s1v = 0.f; }
}

// ---------------- stage 1: fp16 WMMA GEMM, pair-packed, fold fused, double-buffered ----------------
// grid S1TILES, 512 threads (16 warps: 8M x 2N). Tile rows: 64 cos-rows + 64 sin-rows of 64 pairs.
#define ASTR 40
#define BSTR 40
#define CSTR 232
#define SM1_A0 0
#define SM1_A1 10240
#define SM1_B0 20480
#define SM1_B1 38400
#define SM1_TOT 59392          // epilogue Cs (64*232*4) overlays from 0

__global__ void __launch_bounds__(512)
k_s1mma(const float* __restrict__ Hre, const float* __restrict__ Him) {
    extern __shared__ char smem[];
    __half* Abuf[2] = { (__half*)(smem + SM1_A0), (__half*)(smem + SM1_A1) };
    __half* Bbuf[2] = { (__half*)(smem + SM1_B0), (__half*)(smem + SM1_B1) };
    float*  Cs = (float*)(smem);

    int tid = threadIdx.x;
    int tile = blockIdx.x;

    int wid = tid >> 5;
    int wm = wid & 7, wn = wid >> 3;
    int mb = wm * 16, nb = wn * 112;

    wmma::fragment<wmma::accumulator, 16, 16, 16, float> acc[7];
    #pragma unroll
    for (int ni = 0; ni < 7; ni++) wmma::fill_fragment(acc[ni], 0.0f);

    int lc = tid & 63;
    int kq = tid >> 6;                      // 0..7
    int pg = tile*64 + lc;
    bool valid = (pg < NPAIR);
    int pgc = valid ? pg : 0;
    int f  = pgc / 585;
    int lp = pgc - f*585;
    int lgA = lp;
    int lgB = (lp == 0) ? 585 : (KT - lp);
    bool special = (lp == 0);
    const size_t hb = (size_t)f * KF * KT;

    // prologue: fill buffer 0
    {
        #pragma unroll
        for (int j = 0; j < 2; j++) {
            int ka = kq + j*8;
            float c0, c1, s0, s1v;
            buildRows(Hre, Him, hb, ka, lgA, lgB, special, valid, c0, c1, s0, s1v);
            *(__half2*)&Abuf[0][lc*ASTR + 2*ka]      = __floats2half2_rn(c0*ASCALE, c1*ASCALE);
            *(__half2*)&Abuf[0][(64+lc)*ASTR + 2*ka] = __floats2half2_rn(s0*ASCALE, s1v*ASCALE);
        }
        for (int i = tid; i < 896; i += 512) {
            int row = i >> 2, seg = i & 3;
            uint4 v = *(const uint4*)&g_B1h[(size_t)row*KP + seg*8];
            *(uint4*)&Bbuf[0][row*BSTR + seg*8] = v;
        }
    }
    __syncthreads();

    int brow = tid >> 2, bseg = tid & 3;
    int brow2 = (tid+512) >> 2, bseg2 = (tid+512) & 3;

    for (int ch = 0; ch < NCHUNK; ch++) {
        __half* Ah = Abuf[ch & 1];
        __half* Bh = Bbuf[ch & 1];
        bool hn = (ch + 1 < NCHUNK);
        float nA[2][4];
        uint4 nB0, nB1;
        if (hn) {
            #pragma unroll
            for (int j = 0; j < 2; j++) {
                int kg = (ch+1)*16 + kq + j*8;
                buildRows(Hre, Him, hb, kg, lgA, lgB, special, valid,
                          nA[j][0], nA[j][1], nA[j][2], nA[j][3]);
            }
            nB0 = *(const uint4*)&g_B1h[(size_t)brow*KP + (ch+1)*32 + bseg*8];
            if (tid < 384)
                nB1 = *(const uint4*)&g_B1h[(size_t)brow2*KP + (ch+1)*32 + bseg2*8];
        }

        // ks=0 always; ks=1 skipped on the last chunk (k' >= 432 all zero)
        {
            wmma::fragment<wmma::matrix_a, 16, 16, 16, __half, wmma::row_major> a;
            wmma::load_matrix_sync(a, &Ah[mb*ASTR], ASTR);
            #pragma unroll
            for (int ni = 0; ni < 7; ni++) {
                wmma::fragment<wmma::matrix_b, 16, 16, 16, __half, wmma::col_major> b;
                wmma::load_matrix_sync(b, &Bh[(nb + ni*16)*BSTR], BSTR);
                wmma::mma_sync(acc[ni], a, b, acc[ni]);
            }
        }
        if (ch != NCHUNK-1) {
            wmma::fragment<wmma::matrix_a, 16, 16, 16, __half, wmma::row_major> a;
            wmma::load_matrix_sync(a, &Ah[mb*ASTR + 16], ASTR);
            #pragma unroll
            for (int ni = 0; ni < 7; ni++) {
                wmma::fragment<wmma::matrix_b, 16, 16, 16, __half, wmma::col_major> b;
                wmma::load_matrix_sync(b, &Bh[(nb + ni*16)*BSTR + 16], BSTR);
                wmma::mma_sync(acc[ni], a, b, acc[ni]);
            }
        }

        if (hn) {
            __half* An = Abuf[(ch+1) & 1];
            __half* Bn = Bbuf[(ch+1) & 1];
            #pragma unroll
            for (int j = 0; j < 2; j++) {
                int ka = kq + j*8;
                *(__half2*)&An[lc*ASTR + 2*ka]      = __floats2half2_rn(nA[j][0]*ASCALE, nA[j][1]*ASCALE);
                *(__half2*)&An[(64+lc)*ASTR + 2*ka] = __floats2half2_rn(nA[j][2]*ASCALE, nA[j][3]*ASCALE);
            }
            *(uint4*)&Bn[brow*BSTR + bseg*8] = nB0;
            if (tid < 384)
                *(uint4*)&Bn[brow2*BSTR + bseg2*8] = nB1;
        }
        __syncthreads();
    }

    // ---- two-phase epilogue: 64 rows at a time (phase 0 = cos rows, 1 = sin rows) ----
    #pragma unroll
    for (int p = 0; p < 2; p++) {
        if ((wm >> 2) == p) {
            #pragma unroll
            for (int ni = 0; ni < 7; ni++)
                wmma::store_matrix_sync(&Cs[((wm & 3)*16)*CSTR + nb + ni*16], acc[ni],
                                        CSTR, wmma::mem_row_major);
        }
        __syncthreads();
        for (int i = tid; i < 64*28; i += 512) {
            int row = i / 28, c8 = i % 28;
            int pg2 = tile*64 + row;
            if (pg2 < NPAIR) {
                int f2  = pg2 / 585;
                int lp2 = pg2 - f2*585;
                int t = (p == 0) ? ((lp2 == 0) ? 0 : (lp2 + 1))
                                 : ((lp2 == 0) ? 1 : (585 + lp2));
                const float4* src = (const float4*)&Cs[row*CSTR + c8*8];
                float4 v0 = src[0], v1 = src[1];
                __half2 h0 = __floats2half2_rn(v0.x, v0.y);
                __half2 h1 = __floats2half2_rn(v0.z, v0.w);
                __half2 h2 = __floats2half2_rn(v1.x, v1.y);
                __half2 h3 = __floats2half2_rn(v1.z, v1.w);
                uint4 pk;
                pk.x = *(uint32_t*)&h0; pk.y = *(uint32_t*)&h1;
                pk.z = *(uint32_t*)&h2; pk.w = *(uint32_t*)&h3;
                *(uint4*)&g_Vf[(size_t)t*MPAD + (size_t)f2*PP + c8*8] = pk;
            }
        }
        __syncthreads();
    }
}

// ---------------- stage 2: fp16 WMMA GEMM + fused epilogue, double-buffered ----------------
// grid (2 qtiles, 210 mtiles), 512 threads (16 warps: 8M x 2N). qtile0 N=224 (NI=7), qtile1 N=192 (NI=6).
#define A2STR 136
#define B2STR 232
#define S2_A0 0
#define S2_A1 8704
#define S2_B0 17408
#define S2_B1 32256
#define S2_STG 47104
#define S2_TOT 63488

template<int NI>
__device__ __forceinline__ void s2body(int q0, int bx) {
    extern __shared__ char smem[];
    __half* Abuf[2] = { (__half*)(smem + S2_A0), (__half*)(smem + S2_A1) };
    __half* Bbuf[2] = { (__half*)(smem + S2_B0), (__half*)(smem + S2_B1) };
    float*  Stg = (float*)(smem + S2_STG);

    const int NC4 = NI*4;                    // uint4 per B row
    int tid = threadIdx.x;
    int m0 = blockIdx.y * 128;
    int wid = tid >> 5, lane = tid & 31;
    int wm = wid & 7, wn = wid >> 3;
    int mb = wm * 16, nb = wn * NI * 16;

    wmma::fragment<wmma::accumulator, 16, 16, 16, float> acc[NI];
    #pragma unroll
    for (int ni = 0; ni < NI; ni++) wmma::fill_fragment(acc[ni], 0.0f);

    int arow = tid >> 4, aoff = tid & 15;
    int brow = tid / NC4, bcol = tid % NC4;
    int brow2 = (tid+512) / NC4, bcol2 = (tid+512) % NC4;
    bool b2ok = (tid + 512) < 32*NC4;

    // prologue: fill buffer 0
    {
        uint4 v = *(const uint4*)&g_Vf[(size_t)arow*MPAD + m0 + aoff*8];
        *(uint4*)&Abuf[0][arow*A2STR + aoff*8] = v;
        uint4 b0 = *(const uint4*)&g_E2h[(size_t)brow*NQPAD + q0 + bcol*8];
        *(uint4*)&Bbuf[0][brow*B2STR + bcol*8] = b0;
        if (b2ok) {
            uint4 b1 = *(const uint4*)&g_E2h[(size_t)brow2*NQPAD + q0 + bcol2*8];
            *(uint4*)&Bbuf[0][brow2*B2STR + bcol2*8] = b1;
        }
    }
    __syncthreads();

    for (int ch = 0; ch < 37; ch++) {
        __half* As = Abuf[ch & 1];
        __half* Bs = Bbuf[ch & 1];
        bool hn = (ch + 1 < 37);
        uint4 pa, pb0, pb1;
        if (hn) {
            int kb = (ch+1)*32;
            pa  = *(const uint4*)&g_Vf[(size_t)(kb+arow)*MPAD + m0 + aoff*8];
            pb0 = *(const uint4*)&g_E2h[(size_t)(kb+brow)*NQPAD + q0 + bcol*8];
            if (b2ok)
                pb1 = *(const uint4*)&g_E2h[(size_t)(kb+brow2)*NQPAD + q0 + bcol2*8];
        }

        #pragma unroll
        for (int ks = 0; ks < 2; ks++) {
            wmma::fragment<wmma::matrix_a, 16, 16, 16, __half, wmma::col_major> a;
            wmma::load_matrix_sync(a, &As[(ks*16)*A2STR + mb], A2STR);
            #pragma unroll
            for (int ni = 0; ni < NI; ni++) {
                wmma::fragment<wmma::matrix_b, 16, 16, 16, __half, wmma::row_major> b;
                wmma::load_matrix_sync(b, &Bs[(ks*16)*B2STR + nb + ni*16], B2STR);
                wmma::mma_sync(acc[ni], a, b, acc[ni]);
            }
        }

        if (hn) {
            __half* An = Abuf[(ch+1) & 1];
            __half* Bn = Bbuf[(ch+1) & 1];
            *(uint4*)&An[arow*A2STR + aoff*8] = pa;
            *(uint4*)&Bn[brow*B2STR + bcol*8] = pb0;
            if (b2ok)
                *(uint4*)&Bn[brow2*B2STR + bcol2*8] = pb1;
        }
        __syncthreads();
    }

    // ---- fused epilogue: per-warp staging, rescaled clamp-power row sums ----
    float* st = &Stg[wid*256];
    int r0 = lane >> 1, half = lane & 1;
    float rs = 0.f;
    #pragma unroll
    for (int ni = 0; ni < NI; ni++) {
        wmma::store_matrix_sync(st, acc[ni], 16, wmma::mem_row_major);
        __syncwarp();
        int qbase = q0 + nb + ni*16 + half*8;
        #pragma unroll
        for (int c = 0; c < 8; c++) {
            float v = st[r0*16 + half*8 + c];
            if (qbase + c < NTIME) rs += fmaxf(v*v*PSCALE, 1e-8f);
        }
        __syncwarp();
    }
    rs += __shfl_down_sync(0xffffffffu, rs, 1);
    int mrow = mb + r0;
    int m = m0 + mrow;
    int ff = m / PP, p = m - ff*PP;
    bool mok = (p < NFREQ) && (ff < NFILT);
    if (half == 0)
        g_Part[((blockIdx.y*2 + bx)*2 + wn)*128 + mrow] = mok ? rs : 0.f;
}

__global__ void __launch_bounds__(512)
k_s2mma() {
    if (blockIdx.x == 0) s2body<7>(0, 0);
    else                 s2body<6>(224, 1);
}

// ---------------- finalize ----------------
__global__ void k_fin(float* __restrict__ out) {
    int f = threadIdx.x;
    if (f >= NFILT) return;
    float s = 0.f;
    for (int p = 0; p < NFREQ; p++) {
        int m = f*PP + p;
        int mt = m >> 7, r = m & 127;
        #pragma unroll
        for (int sl = 0; sl < 4; sl++)
            s += g_Part[(mt*4 + sl)*128 + r];
    }
    out[f] = s * (1.0f / (float)(NFREQ*NTIME));
}

// ---------------- launch ----------------
extern "C" void kernel_launch(void* const* d_in, const int* in_sizes, int n_in,
                              void* d_out, int out_size) {
    (void)in_sizes; (void)n_in; (void)out_size;
    const float* x   = (const float*)d_in[0];
    const float* Hre = (const float*)d_in[1];
    const float* Him = (const float*)d_in[2];
    float* out = (float*)d_out;

    cudaFuncSetAttribute(k_s1mma, cudaFuncAttributeMaxDynamicSharedMemorySize, SM1_TOT);
    cudaFuncSetAttribute(k_s2mma, cudaFuncAttributeMaxDynamicSharedMemorySize, S2_TOT);

    k_tw    <<<5, 256>>>();
    k_B1    <<<(PP*KP + 255)/256, 256>>>();
    k_E2    <<<(KFOLD*NQPAD + 255)/256, 256>>>();
    k_P     <<<dim3(5, NFREQ), 256>>>(x);
    k_X     <<<dim3(5, KF),    256>>>();
    k_s1mma <<<S1TILES, 512, SM1_TOT>>>(Hre, Him);
    k_s2mma <<<dim3(2, S2MT), 512, S2_TOT>>>();
    k_fin   <<<1, 128>>>(out);
}

// round 17
// speedup vs baseline: 1.3721x; 1.0553x over previous
#include <cuda_runtime.h>
#include <cuda_fp16.h>
#include <mma.h>
#include <math.h>
#include <stdint.h>

using namespace nvcuda;

// Problem dims
#define NFREQ 211
#define NTIME 390
#define KF    422
#define KT    1170
#define NFILT 119
#define PP    216            // padded p stride per filter (Vf layout)
#define PPB   224            // stage-1 GEMM N (B rows 211..223 zero)
#define MPAD  25728          // 201*128 >= 119*216
#define KFOLD 1170
#define K2P   1184           // stage-2 padded K (37*32)
#define NQPAD 448
#define KP    448            // stage-1 K' (S/iT interleaved)
#define NCHUNK 14            // stage-1 K' chunks of 32 (last chunk half)
#define NPAIR  69615         // 585 * 119 row-pairs
#define S1TILES 1088         // ceil(NPAIR/64)
#define S2MT  201            // stage-2 m-tiles of 128

#define ASCALE  0x1p-12f     // fp16 range guard on stage-1 A operand
#define PSCALE  0x1p24f      // undo (ASCALE^2) in the power epilogue

// ---------------- device scratch ----------------
__device__ __align__(8)  float2 g_twT[KT];                 // e^{-2pi i j/KT}
__device__ __align__(8)  float2 g_twF[KF];                 // e^{-2pi i j/KF}
__device__ __align__(16) __half g_B1h[(size_t)PPB*KP];     // stage-1 coeffs [p][k']
__device__ __align__(16) __half g_E2h[(size_t)K2P*NQPAD];  // rows >=1170 stay 0
__device__ float2 g_P[(size_t)216*KT];                     // rows 211..215 stay 0 (pad)
__device__ float2 g_X[(size_t)KF*KT];
__device__ __align__(16) __half g_Vf[(size_t)K2P*MPAD];    // folded V (scaled), pad stays 0
__device__ float  g_Part[S2MT*4*128];

// ---------------- builders ----------------
__global__ void k_tw() {
    int i = blockIdx.x*256 + threadIdx.x;
    if (i < KT) { double s,c; sincospi(2.0*i/KT, &s, &c); g_twT[i] = make_float2((float)c, (float)(-s)); }
    if (i < KF) { double s,c; sincospi(2.0*i/KF, &s, &c); g_twF[i] = make_float2((float)c, (float)(-s)); }
}
__global__ void k_B1() {
    int i = blockIdx.x*256 + threadIdx.x;
    if (i >= PPB*KP) return;
    int p = i / KP, k = i % KP;
    int kap = k >> 1; int iss = k & 1;
    float v = 0.f;
    const float inv = 1.0f/(float)KF;
    if (p < NFREQ && kap <= 211) {
        if (kap == 0)        v = iss ? 0.f : inv;
        else if (kap == 211) v = iss ? 0.f : ((p & 1) ? -inv : inv);
        else {
            int r = (kap*p) % KF;
            float s, c; sincospif(2.0f*(float)r/(float)KF, &s, &c);
            v = (iss ? s : c) * inv;
        }
    }
    g_B1h[i] = __float2half(v);
}
__global__ void k_E2() {
    int i = blockIdx.x*256 + threadIdx.x;
    if (i >= KFOLD*NQPAD) return;
    int kap = i / NQPAD, q = i % NQPAD;
    float val = 0.f;
    const float inv = 1.0f/(float)KT;
    if (q < NTIME) {
        if (kap == 0)      val = inv;
        else if (kap == 1) val = (q & 1) ? -inv : inv;
        else if (kap < 586) {
            int l = kap - 1;
            int r = (l*q) % KT;
            float s, c; sincospif(2.0f*(float)r/(float)KT, &s, &c);
            val = c * inv;
        } else {
            int l = kap - 585;
            int r = (l*q) % KT;
            float s, c; sincospif(2.0f*(float)r/(float)KT, &s, &c);
            val = -s * inv;
        }
    }
    g_E2h[(size_t)kap*NQPAD + q] = __float2half(val);
}

// ---------------- stage 0: X = fft2(pad(100*x)), 8-rotator DFT, table init ----------------
__global__ void k_P(const float* __restrict__ x) {
    __shared__ float xs[392];
    int tid = threadIdx.x;
    int u = blockIdx.y;
    for (int i = tid; i < 392; i += 256) xs[i] = (i < NTIME) ? x[u*NTIME + i] * 100.0f : 0.f;
    __syncthreads();
    int l = blockIdx.x*256 + tid;
    if (l >= KT) return;
    float tr[8], ti[8], ar[8], ai[8];
    #pragma unroll
    for (int j = 0; j < 8; j++) {
        float2 t = g_twT[(int)(((long long)j*l) % KT)];
        tr[j] = t.x; ti[j] = t.y;
        ar[j] = 0.f; ai[j] = 0.f;
    }
    float2 w8 = g_twT[(8*l) % KT];
    float w8r = w8.x, w8i = w8.y;
    for (int v = 0; v < 49; v++) {
        #pragma unroll
        for (int j = 0; j < 8; j++) {
            float xv = xs[v*8 + j];
            ar[j] = fmaf(xv, tr[j], ar[j]);
            ai[j] = fmaf(xv, ti[j], ai[j]);
            float nr = fmaf(tr[j], w8r, -ti[j]*w8i);
            float ni = fmaf(tr[j], w8i,  ti[j]*w8r);
            tr[j] = nr; ti[j] = ni;
        }
    }
    float sr = ((ar[0]+ar[1])+(ar[2]+ar[3])) + ((ar[4]+ar[5])+(ar[6]+ar[7]));
    float si = ((ai[0]+ai[1])+(ai[2]+ai[3])) + ((ai[4]+ai[5])+(ai[6]+ai[7]));
    g_P[(size_t)u*KT + l] = make_float2(sr, si);
}
__global__ void k_X() {
    int tid = threadIdx.x;
    int l = blockIdx.x*256 + tid;
    int k = blockIdx.y;
    if (l >= KT) return;
    float tr[8], ti[8], xr[8], xi[8];
    #pragma unroll
    for (int j = 0; j < 8; j++) {
        float2 t = g_twF[(int)(((long long)j*k) % KF)];
        tr[j] = t.x; ti[j] = t.y;
        xr[j] = 0.f; xi[j] = 0.f;
    }
    float2 w8 = g_twF[(8*k) % KF];
    float w8r = w8.x, w8i = w8.y;
    for (int v = 0; v < 27; v++) {
        #pragma unroll
        for (int j = 0; j < 8; j++) {
            float2 P = g_P[(size_t)(v*8 + j)*KT + l];   // rows 211..215 = zeros (pad)
            xr[j] += P.x*tr[j] - P.y*ti[j];
            xi[j] += P.x*ti[j] + P.y*tr[j];
            float nr = fmaf(tr[j], w8r, -ti[j]*w8i);
            float ni = fmaf(tr[j], w8i,  ti[j]*w8r);
            tr[j] = nr; ti[j] = ni;
        }
    }
    float sr = ((xr[0]+xr[1])+(xr[2]+xr[3])) + ((xr[4]+xr[5])+(xr[6]+xr[7]));
    float si = ((xi[0]+xi[1])+(xi[2]+xi[3])) + ((xi[4]+xi[5])+(xi[6]+xi[7]));
    g_X[(size_t)k*KT + l] = make_float2(sr, si);
}

// freq-fold of H*X at (kap kg, time lg); H streamed (read-once) via __ldcs
__device__ __forceinline__ void foldA(const float* __restrict__ Hre, const float* __restrict__ Him,
                                      size_t hb, int kg, int lg,
                                      float &Sx, float &Sy, float &iTx, float &iTy) {
    Sx = Sy = iTx = iTy = 0.f;
    if (kg <= 211) {
        float2 X = g_X[(size_t)kg*KT + lg];
        float hr = __ldcs(&Hre[hb + (size_t)kg*KT + lg]);
        float hi = __ldcs(&Him[hb + (size_t)kg*KT + lg]);
        float war = hr*X.x - hi*X.y;
        float wai = hr*X.y + hi*X.x;
        if (kg >= 1 && kg <= 210) {
            int km = KF - kg;
            float2 X2 = g_X[(size_t)km*KT + lg];
            float hr2 = __ldcs(&Hre[hb + (size_t)km*KT + lg]);
            float hi2 = __ldcs(&Him[hb + (size_t)km*KT + lg]);
            float wbr = hr2*X2.x - hi2*X2.y;
            float wbi = hr2*X2.y + hi2*X2.x;
            Sx = war + wbr; Sy = wai + wbi;
            float Tx = war - wbr, Ty = wai - wbi;
            iTx = -Ty; iTy = Tx;
        } else { Sx = war; Sy = wai; }
    }
}
// one pair: cos row (c0,c1) and sin row (s0,s1); special pair (lp==0) packs cos@0 + cos@585
__device__ __forceinline__ void buildRows(const float* __restrict__ Hre, const float* __restrict__ Him,
                                          size_t hb, int kg, int lgA, int lgB, bool special, bool valid,
                                          float &c0, float &c1, float &s0, float &s1v) {
    float SxA,SyA,iTxA,iTyA, SxB,SyB,iTxB,iTyB;
    foldA(Hre, Him, hb, kg, lgA, SxA, SyA, iTxA, iTyA);
    foldA(Hre, Him, hb, kg, lgB, SxB, SyB, iTxB, iTyB);
    if (special) { c0 = SxA; c1 = iTxA; s0 = SxB; s1v = iTxB; }
    else         { c0 = SxA+SxB; c1 = iTxA+iTxB; s0 = SyA-SyB; s1v = iTyA-iTyB; }
    if (!valid)  { c0 = c1 = s0 = s1v = 0.f; }
}

// ---------------- stage 1: fp16 WMMA GEMM, pair-packed, fold fused, double-buffered ----------------
// grid S1TILES, 512 threads (16 warps: 8M x 2N). Tile rows: 64 cos-rows + 64 sin-rows of 64 pairs.
#define ASTR 40
#define BSTR 40
#define CSTR 232
#define SM1_A0 0
#define SM1_A1 10240
#define SM1_B0 20480
#define SM1_B1 38400
#define SM1_TOT 59392          // epilogue Cs (64*232*4) overlays from 0

__global__ void __launch_bounds__(512)
k_s1mma(const float* __restrict__ Hre, const float* __restrict__ Him) {
    extern __shared__ char smem[];
    __half* Abuf[2] = { (__half*)(smem + SM1_A0), (__half*)(smem + SM1_A1) };
    __half* Bbuf[2] = { (__half*)(smem + SM1_B0), (__half*)(smem + SM1_B1) };
    float*  Cs = (float*)(smem);

    int tid = threadIdx.x;
    int tile = blockIdx.x;

    int wid = tid >> 5;
    int wm = wid & 7, wn = wid >> 3;
    int mb = wm * 16, nb = wn * 112;

    wmma::fragment<wmma::accumulator, 16, 16, 16, float> acc[7];
    #pragma unroll
    for (int ni = 0; ni < 7; ni++) wmma::fill_fragment(acc[ni], 0.0f);

    int lc = tid & 63;
    int kq = tid >> 6;                      // 0..7
    int pg = tile*64 + lc;
    bool valid = (pg < NPAIR);
    int pgc = valid ? pg : 0;
    int f  = pgc / 585;
    int lp = pgc - f*585;
    int lgA = lp;
    int lgB = (lp == 0) ? 585 : (KT - lp);
    bool special = (lp == 0);
    const size_t hb = (size_t)f * KF * KT;

    // prologue: fill buffer 0
    {
        #pragma unroll
        for (int j = 0; j < 2; j++) {
            int ka = kq + j*8;
            float c0, c1, s0, s1v;
            buildRows(Hre, Him, hb, ka, lgA, lgB, special, valid, c0, c1, s0, s1v);
            *(__half2*)&Abuf[0][lc*ASTR + 2*ka]      = __floats2half2_rn(c0*ASCALE, c1*ASCALE);
            *(__half2*)&Abuf[0][(64+lc)*ASTR + 2*ka] = __floats2half2_rn(s0*ASCALE, s1v*ASCALE);
        }
        for (int i = tid; i < 896; i += 512) {
            int row = i >> 2, seg = i & 3;
            uint4 v = *(const uint4*)&g_B1h[(size_t)row*KP + seg*8];
            *(uint4*)&Bbuf[0][row*BSTR + seg*8] = v;
        }
    }
    __syncthreads();

    int brow = tid >> 2, bseg = tid & 3;
    int brow2 = (tid+512) >> 2, bseg2 = (tid+512) & 3;

    for (int ch = 0; ch < NCHUNK; ch++) {
        __half* Ah = Abuf[ch & 1];
        __half* Bh = Bbuf[ch & 1];
        bool hn = (ch + 1 < NCHUNK);
        float nA[2][4];
        uint4 nB0, nB1;
        if (hn) {
            #pragma unroll
            for (int j = 0; j < 2; j++) {
                int kg = (ch+1)*16 + kq + j*8;
                buildRows(Hre, Him, hb, kg, lgA, lgB, special, valid,
                          nA[j][0], nA[j][1], nA[j][2], nA[j][3]);
            }
            nB0 = *(const uint4*)&g_B1h[(size_t)brow*KP + (ch+1)*32 + bseg*8];
            if (tid < 384)
                nB1 = *(const uint4*)&g_B1h[(size_t)brow2*KP + (ch+1)*32 + bseg2*8];
        }

        // ks=0 always; ks=1 skipped on the last chunk (k' >= 432 all zero)
        {
            wmma::fragment<wmma::matrix_a, 16, 16, 16, __half, wmma::row_major> a;
            wmma::load_matrix_sync(a, &Ah[mb*ASTR], ASTR);
            #pragma unroll
            for (int ni = 0; ni < 7; ni++) {
                wmma::fragment<wmma::matrix_b, 16, 16, 16, __half, wmma::col_major> b;
                wmma::load_matrix_sync(b, &Bh[(nb + ni*16)*BSTR], BSTR);
                wmma::mma_sync(acc[ni], a, b, acc[ni]);
            }
        }
        if (ch != NCHUNK-1) {
            wmma::fragment<wmma::matrix_a, 16, 16, 16, __half, wmma::row_major> a;
            wmma::load_matrix_sync(a, &Ah[mb*ASTR + 16], ASTR);
            #pragma unroll
            for (int ni = 0; ni < 7; ni++) {
                wmma::fragment<wmma::matrix_b, 16, 16, 16, __half, wmma::col_major> b;
                wmma::load_matrix_sync(b, &Bh[(nb + ni*16)*BSTR + 16], BSTR);
                wmma::mma_sync(acc[ni], a, b, acc[ni]);
            }
        }

        if (hn) {
            __half* An = Abuf[(ch+1) & 1];
            __half* Bn = Bbuf[(ch+1) & 1];
            #pragma unroll
            for (int j = 0; j < 2; j++) {
                int ka = kq + j*8;
                *(__half2*)&An[lc*ASTR + 2*ka]      = __floats2half2_rn(nA[j][0]*ASCALE, nA[j][1]*ASCALE);
                *(__half2*)&An[(64+lc)*ASTR + 2*ka] = __floats2half2_rn(nA[j][2]*ASCALE, nA[j][3]*ASCALE);
            }
            *(uint4*)&Bn[brow*BSTR + bseg*8] = nB0;
            if (tid < 384)
                *(uint4*)&Bn[brow2*BSTR + bseg2*8] = nB1;
        }
        __syncthreads();
    }

    // ---- two-phase epilogue: 64 rows at a time (phase 0 = cos rows, 1 = sin rows) ----
    #pragma unroll
    for (int p = 0; p < 2; p++) {
        if ((wm >> 2) == p) {
            #pragma unroll
            for (int ni = 0; ni < 7; ni++)
                wmma::store_matrix_sync(&Cs[((wm & 3)*16)*CSTR + nb + ni*16], acc[ni],
                                        CSTR, wmma::mem_row_major);
        }
        __syncthreads();
        for (int i = tid; i < 64*27; i += 512) {
            int row = i / 27, c8 = i % 27;
            int pg2 = tile*64 + row;
            if (pg2 < NPAIR) {
                int f2  = pg2 / 585;
                int lp2 = pg2 - f2*585;
                int t = (p == 0) ? ((lp2 == 0) ? 0 : (lp2 + 1))
                                 : ((lp2 == 0) ? 1 : (585 + lp2));
                const float4* src = (const float4*)&Cs[row*CSTR + c8*8];
                float4 v0 = src[0], v1 = src[1];
                __half2 h0 = __floats2half2_rn(v0.x, v0.y);
                __half2 h1 = __floats2half2_rn(v0.z, v0.w);
                __half2 h2 = __floats2half2_rn(v1.x, v1.y);
                __half2 h3 = __floats2half2_rn(v1.z, v1.w);
                uint4 pk;
                pk.x = *(uint32_t*)&h0; pk.y = *(uint32_t*)&h1;
                pk.z = *(uint32_t*)&h2; pk.w = *(uint32_t*)&h3;
                *(uint4*)&g_Vf[(size_t)t*MPAD + (size_t)f2*PP + c8*8] = pk;
            }
        }
        __syncthreads();
    }
}

// ---------------- stage 2: fp16 WMMA GEMM + fused epilogue, double-buffered ----------------
// grid (2 qtiles, 201 mtiles), 512 threads (16 warps: 8M x 2N). qtile0 N=224 (NI=7), qtile1 N=192 (NI=6).
#define A2STR 136
#define B2STR 232
#define S2_A0 0
#define S2_A1 8704
#define S2_B0 17408
#define S2_B1 32256
#define S2_STG 47104
#define S2_TOT 63488

template<int NI>
__device__ __forceinline__ void s2body(int q0, int bx) {
    extern __shared__ char smem[];
    __half* Abuf[2] = { (__half*)(smem + S2_A0), (__half*)(smem + S2_A1) };
    __half* Bbuf[2] = { (__half*)(smem + S2_B0), (__half*)(smem + S2_B1) };
    float*  Stg = (float*)(smem + S2_STG);

    const int NC4 = NI*4;                    // uint4 per B row
    int tid = threadIdx.x;
    int m0 = blockIdx.y * 128;
    int wid = tid >> 5, lane = tid & 31;
    int wm = wid & 7, wn = wid >> 3;
    int mb = wm * 16, nb = wn * NI * 16;

    wmma::fragment<wmma::accumulator, 16, 16, 16, float> acc[NI];
    #pragma unroll
    for (int ni = 0; ni < NI; ni++) wmma::fill_fragment(acc[ni], 0.0f);

    int arow = tid >> 4, aoff = tid & 15;
    int brow = tid / NC4, bcol = tid % NC4;
    int brow2 = (tid+512) / NC4, bcol2 = (tid+512) % NC4;
    bool b2ok = (tid + 512) < 32*NC4;

    // prologue: fill buffer 0
    {
        uint4 v = *(const uint4*)&g_Vf[(size_t)arow*MPAD + m0 + aoff*8];
        *(uint4*)&Abuf[0][arow*A2STR + aoff*8] = v;
        uint4 b0 = *(const uint4*)&g_E2h[(size_t)brow*NQPAD + q0 + bcol*8];
        *(uint4*)&Bbuf[0][brow*B2STR + bcol*8] = b0;
        if (b2ok) {
            uint4 b1 = *(const uint4*)&g_E2h[(size_t)brow2*NQPAD + q0 + bcol2*8];
            *(uint4*)&Bbuf[0][brow2*B2STR + bcol2*8] = b1;
        }
    }
    __syncthreads();

    for (int ch = 0; ch < 37; ch++) {
        __half* As = Abuf[ch & 1];
        __half* Bs = Bbuf[ch & 1];
        bool hn = (ch + 1 < 37);
        uint4 pa, pb0, pb1;
        if (hn) {
            int kb = (ch+1)*32;
            pa  = *(const uint4*)&g_Vf[(size_t)(kb+arow)*MPAD + m0 + aoff*8];
            pb0 = *(const uint4*)&g_E2h[(size_t)(kb+brow)*NQPAD + q0 + bcol*8];
            if (b2ok)
                pb1 = *(const uint4*)&g_E2h[(size_t)(kb+brow2)*NQPAD + q0 + bcol2*8];
        }

        #pragma unroll
        for (int ks = 0; ks < 2; ks++) {
            wmma::fragment<wmma::matrix_a, 16, 16, 16, __half, wmma::col_major> a;
            wmma::load_matrix_sync(a, &As[(ks*16)*A2STR + mb], A2STR);
            #pragma unroll
            for (int ni = 0; ni < NI; ni++) {
                wmma::fragment<wmma::matrix_b, 16, 16, 16, __half, wmma::row_major> b;
                wmma::load_matrix_sync(b, &Bs[(ks*16)*B2STR + nb + ni*16], B2STR);
                wmma::mma_sync(acc[ni], a, b, acc[ni]);
            }
        }

        if (hn) {
            __half* An = Abuf[(ch+1) & 1];
            __half* Bn = Bbuf[(ch+1) & 1];
            *(uint4*)&An[arow*A2STR + aoff*8] = pa;
            *(uint4*)&Bn[brow*B2STR + bcol*8] = pb0;
            if (b2ok)
                *(uint4*)&Bn[brow2*B2STR + bcol2*8] = pb1;
        }
        __syncthreads();
    }

    // ---- fused epilogue: per-warp staging, rescaled clamp-power row sums ----
    float* st = &Stg[wid*256];
    int r0 = lane >> 1, half = lane & 1;
    float rs = 0.f;
    #pragma unroll
    for (int ni = 0; ni < NI; ni++) {
        wmma::store_matrix_sync(st, acc[ni], 16, wmma::mem_row_major);
        __syncwarp();
        int qbase = q0 + nb + ni*16 + half*8;
        #pragma unroll
        for (int c = 0; c < 8; c++) {
            float v = st[r0*16 + half*8 + c];
            if (qbase + c < NTIME) rs += fmaxf(v*v*PSCALE, 1e-8f);
        }
        __syncwarp();
    }
    rs += __shfl_down_sync(0xffffffffu, rs, 1);
    int mrow = mb + r0;
    int m = m0 + mrow;
    int ff = m / PP, p = m - ff*PP;
    bool mok = (p < NFREQ) && (ff < NFILT);
    if (half == 0)
        g_Part[((blockIdx.y*2 + bx)*2 + wn)*128 + mrow] = mok ? rs : 0.f;
}

__global__ void __launch_bounds__(512)
k_s2mma() {
    if (blockIdx.x == 0) s2body<7>(0, 0);
    else                 s2body<6>(224, 1);
}

// ---------------- finalize ----------------
__global__ void k_fin(float* __restrict__ out) {
    int f = threadIdx.x;
    if (f >= NFILT) return;
    float s = 0.f;
    for (int p = 0; p < NFREQ; p++) {
        int m = f*PP + p;
        int mt = m >> 7, r = m & 127;
        #pragma unroll
        for (int sl = 0; sl < 4; sl++)
            s += g_Part[(mt*4 + sl)*128 + r];
    }
    out[f] = s * (1.0f / (float)(NFREQ*NTIME));
}

// ---------------- launch ----------------
extern "C" void kernel_launch(void* const* d_in, const int* in_sizes, int n_in,
                              void* d_out, int out_size) {
    (void)in_sizes; (void)n_in; (void)out_size;
    const float* x   = (const float*)d_in[0];
    const float* Hre = (const float*)d_in[1];
    const float* Him = (const float*)d_in[2];
    float* out = (float*)d_out;

    cudaFuncSetAttribute(k_s1mma, cudaFuncAttributeMaxDynamicSharedMemorySize, SM1_TOT);
    cudaFuncSetAttribute(k_s2mma, cudaFuncAttributeMaxDynamicSharedMemorySize, S2_TOT);

    k_tw    <<<5, 256>>>();
    k_B1    <<<(PPB*KP + 255)/256, 256>>>();
    k_E2    <<<(KFOLD*NQPAD + 255)/256, 256>>>();
    k_P     <<<dim3(5, NFREQ), 256>>>(x);
    k_X     <<<dim3(5, KF),    256>>>();
    k_s1mma <<<S1TILES, 512, SM1_TOT>>>(Hre, Him);
    k_s2mma <<<dim3(2, S2MT), 512, S2_TOT>>>();
    k_fin   <<<1, 128>>>(out);
}